// round 5
// baseline (speedup 1.0000x reference)
#include <cuda_runtime.h>
#include <cuda_bf16.h>
#include <math.h>
#include <stdint.h>

#define BB 8
#define LL 2048
#define DD 512
#define HH 8
#define DH 64
#define DFF 2048
#define UU 40
#define NBH (BB*HH)

// ---------------- scratch (no allocs allowed) ----------------
__device__ float g_q[NBH*LL*DH];     // [bh][l][d]  fp32
__device__ float g_k[NBH*LL*DH];
__device__ float g_v[NBH*LL*DH];
__device__ __nv_bfloat16 g_qh[NBH*LL*DH];   // bf16 split hi/lo
__device__ __nv_bfloat16 g_ql[NBH*LL*DH];
__device__ __nv_bfloat16 g_kh[NBH*LL*DH];
__device__ __nv_bfloat16 g_kl[NBH*LL*DH];
__device__ float g_M[NBH*LL];
__device__ float g_ksum[NBH*DH];
__device__ float g_vmean[NBH*DH];
__device__ int   g_topidx[NBH*UU];
__device__ float g_topout[NBH*UU*DH];

__device__ __forceinline__ uint32_t smem_u32(const void* p) {
    uint32_t a;
    asm("{ .reg .u64 t; cvta.to.shared.u64 t, %1; cvt.u32.u64 %0, t; }"
        : "=r"(a) : "l"(p));
    return a;
}
#define SWZ(b) ((b) ^ (((b) >> 3) & 0x70))

// ================= Kernel 1: QKV projection (fp32) + bf16 split emit =========
__global__ __launch_bounds__(256) void qkv_kernel(
    const float* __restrict__ x,
    const float* __restrict__ Wq, const float* __restrict__ bq,
    const float* __restrict__ Wk, const float* __restrict__ bk,
    const float* __restrict__ Wv, const float* __restrict__ bv)
{
    const int z = blockIdx.z;
    const float* __restrict__ W    = (z==0) ? Wq : (z==1 ? Wk : Wv);
    const float* __restrict__ bias = (z==0) ? bq : (z==1 ? bk : bv);
    float* __restrict__ outp       = (z==0) ? g_q : (z==1 ? g_k : g_v);

    __shared__ float Xs[16][132];
    __shared__ float Ws[16][68];

    const int m0 = blockIdx.x * 128;
    const int n0 = blockIdx.y * 64;
    const int tid = threadIdx.x;
    const int tn = tid & 15;
    const int tm = tid >> 4;

    float acc[8][4];
    #pragma unroll
    for (int i = 0; i < 8; i++)
        #pragma unroll
        for (int j = 0; j < 4; j++) acc[i][j] = 0.f;

    for (int k0 = 0; k0 < 512; k0 += 16) {
        #pragma unroll
        for (int it = 0; it < 2; it++) {
            int idx = tid + it*256;
            int r = idx >> 2, c = idx & 3;
            float4 xv = *(const float4*)&x[(size_t)(m0 + r)*512 + k0 + c*4];
            Xs[c*4+0][r] = xv.x; Xs[c*4+1][r] = xv.y;
            Xs[c*4+2][r] = xv.z; Xs[c*4+3][r] = xv.w;
        }
        {
            int r = tid >> 4, c = tid & 15;
            float4 wv = *(const float4*)&W[(size_t)(k0 + r)*512 + n0 + c*4];
            *(float4*)&Ws[r][c*4] = wv;
        }
        __syncthreads();
        #pragma unroll
        for (int kk = 0; kk < 16; kk++) {
            float4 a0 = *(float4*)&Xs[kk][tm*8];
            float4 a1 = *(float4*)&Xs[kk][tm*8+4];
            float4 b0 = *(float4*)&Ws[kk][tn*4];
            float am[8] = {a0.x,a0.y,a0.z,a0.w,a1.x,a1.y,a1.z,a1.w};
            float bn[4] = {b0.x,b0.y,b0.z,b0.w};
            #pragma unroll
            for (int i = 0; i < 8; i++)
                #pragma unroll
                for (int j = 0; j < 4; j++)
                    acc[i][j] = fmaf(am[i], bn[j], acc[i][j]);
        }
        __syncthreads();
    }

    const int h = n0 >> 6;
    float4 b4 = *(const float4*)&bias[n0 + tn*4];
    __nv_bfloat16* hp = (z==0) ? g_qh : g_kh;
    __nv_bfloat16* lp = (z==0) ? g_ql : g_kl;
    #pragma unroll
    for (int i = 0; i < 8; i++) {
        int r  = m0 + tm*8 + i;
        int bb = r >> 11, l = r & 2047;
        size_t base = ((size_t)(bb*HH + h)*LL + l)*64 + tn*4;
        float o[4] = {acc[i][0]+b4.x, acc[i][1]+b4.y, acc[i][2]+b4.z, acc[i][3]+b4.w};
        *(float4*)&outp[base] = make_float4(o[0],o[1],o[2],o[3]);
        if (z <= 1) {
            __nv_bfloat16 hi[4], lo[4];
            #pragma unroll
            for (int j = 0; j < 4; j++) {
                hi[j] = __float2bfloat16_rn(o[j]);
                lo[j] = __float2bfloat16_rn(o[j] - __bfloat162float(hi[j]));
            }
            *(__nv_bfloat162*)&hp[base]   = __nv_bfloat162(hi[0], hi[1]);
            *(__nv_bfloat162*)&hp[base+2] = __nv_bfloat162(hi[2], hi[3]);
            *(__nv_bfloat162*)&lp[base]   = __nv_bfloat162(lo[0], lo[1]);
            *(__nv_bfloat162*)&lp[base+2] = __nv_bfloat162(lo[2], lo[3]);
        }
    }
}

// ================= Kernel 2: key-sum & value-mean =================
__global__ __launch_bounds__(256) void stats_kernel()
{
    const int bh = blockIdx.x;
    const int tid = threadIdx.x;
    const int d = tid & 63, p = tid >> 6;
    float ks = 0.f, vs = 0.f;
    for (int s = p*512; s < p*512 + 512; s++) {
        ks += g_k[((size_t)bh*LL + s)*64 + d];
        vs += g_v[((size_t)bh*LL + s)*64 + d];
    }
    __shared__ float rk[256], rv[256];
    rk[tid] = ks; rv[tid] = vs;
    __syncthreads();
    if (p == 0) {
        float K4 = rk[d] + rk[64+d] + rk[128+d] + rk[192+d];
        float V4 = rv[d] + rv[64+d] + rv[128+d] + rv[192+d];
        g_ksum[bh*64 + d]  = K4;
        g_vmean[bh*64 + d] = V4 * (1.0f/LL);
    }
}

// ================= Kernel 3: QK^T row-max via mma.sync (HMMA bf16) ==========
// block = (q-tile 128, bh), 256 thr / 8 warps, warp w owns q-rows 16w..16w+15.
// Precision split: S ~= qh*kh + qh*kl + ql*kh, fp32 accum. Mean term exact.
#define MP_QH 0
#define MP_QL 16384
#define MP_KH 32768
#define MP_KL 49152
#define MP_KS 65536
#define MP_SMEM (65536 + 256)

__device__ __forceinline__ void ldmA(uint32_t* a, uint32_t addr) {
    asm volatile("ldmatrix.sync.aligned.m8n8.x4.shared.b16 {%0,%1,%2,%3}, [%4];"
        : "=r"(a[0]),"=r"(a[1]),"=r"(a[2]),"=r"(a[3]) : "r"(addr));
}
__device__ __forceinline__ void ldmB(uint32_t* b, uint32_t addr) {
    asm volatile("ldmatrix.sync.aligned.m8n8.x2.shared.b16 {%0,%1}, [%2];"
        : "=r"(b[0]),"=r"(b[1]) : "r"(addr));
}
__device__ __forceinline__ void mma16816(float* c, const uint32_t* a, const uint32_t* b) {
    asm volatile(
        "mma.sync.aligned.m16n8k16.row.col.f32.bf16.bf16.f32 "
        "{%0,%1,%2,%3}, {%4,%5,%6,%7}, {%8,%9}, {%0,%1,%2,%3};"
        : "+f"(c[0]),"+f"(c[1]),"+f"(c[2]),"+f"(c[3])
        : "r"(a[0]),"r"(a[1]),"r"(a[2]),"r"(a[3]), "r"(b[0]),"r"(b[1]));
}

__global__ __launch_bounds__(256) void maxpass_mma_kernel()
{
    extern __shared__ char smem[];
    const uint32_t sb = smem_u32(smem);
    const int tid = threadIdx.x, wid = tid >> 5, lane = tid & 31;
    const int bh = blockIdx.y, q0 = blockIdx.x * 128;

    if (tid < 64) *(float*)(smem + MP_KS + tid*4) = g_ksum[bh*64 + tid];

    // Q hi/lo tiles, SW128 swizzled: 1024 16B chunks each
    {
        const char* qh = (const char*)(g_qh + ((size_t)bh*LL + q0)*64);
        const char* ql = (const char*)(g_ql + ((size_t)bh*LL + q0)*64);
        #pragma unroll
        for (int it = 0; it < 4; it++) {
            int byte = (tid + it*256) * 16;
            int sw = SWZ(byte);
            *(uint4*)(smem + MP_QH + sw) = *(const uint4*)(qh + byte);
            *(uint4*)(smem + MP_QL + sw) = *(const uint4*)(ql + byte);
        }
    }

    // per-lane ldmatrix addresses (byte offsets within a 128x128B tile)
    const int ag = lane >> 3, ar = lane & 7;
    const int arow  = wid*16 + ((ag & 1) << 3) + ar;   // A: q-row
    const int ahalf = (ag >> 1) << 3;                  // A: d sub-offset 0/8
    const int bl = lane & 15;
    const int brow  = bl & 7;                          // B: key within block
    const int bhalf = (bl >> 3) << 3;

    float acc[16][4];
    float rmax0 = -INFINITY, rmax1 = -INFINITY;

    for (int kt = 0; kt < LL/128; kt++) {
        __syncthreads();   // prev-tile compute done before overwrite
        {
            const char* kh = (const char*)(g_kh + ((size_t)bh*LL + kt*128)*64);
            const char* kl = (const char*)(g_kl + ((size_t)bh*LL + kt*128)*64);
            #pragma unroll
            for (int it = 0; it < 4; it++) {
                int byte = (tid + it*256) * 16;
                int sw = SWZ(byte);
                *(uint4*)(smem + MP_KH + sw) = *(const uint4*)(kh + byte);
                *(uint4*)(smem + MP_KL + sw) = *(const uint4*)(kl + byte);
            }
        }
        __syncthreads();

        #pragma unroll
        for (int nb = 0; nb < 16; nb++)
            #pragma unroll
            for (int j = 0; j < 4; j++) acc[nb][j] = 0.f;

        #pragma unroll
        for (int kc = 0; kc < 4; kc++) {
            uint32_t Ah[4], Al[4];
            {
                int byte = arow*128 + (kc*16 + ahalf)*2;
                int sw = SWZ(byte);
                ldmA(Ah, sb + MP_QH + sw);
                ldmA(Al, sb + MP_QL + sw);
            }
            #pragma unroll
            for (int nb = 0; nb < 16; nb++) {
                uint32_t Bh[2], Bl[2];
                int byte = (nb*8 + brow)*128 + (kc*16 + bhalf)*2;
                int sw = SWZ(byte);
                ldmB(Bh, sb + MP_KH + sw);
                ldmB(Bl, sb + MP_KL + sw);
                mma16816(acc[nb], Ah, Bh);
                mma16816(acc[nb], Ah, Bl);
                mma16816(acc[nb], Al, Bh);
            }
        }

        #pragma unroll
        for (int nb = 0; nb < 16; nb++) {
            rmax0 = fmaxf(rmax0, fmaxf(acc[nb][0], acc[nb][1]));
            rmax1 = fmaxf(rmax1, fmaxf(acc[nb][2], acc[nb][3]));
        }
    }

    // mean term: (qh+ql) . ksum, distributed over the 4 lanes of each row-group
    const int r0 = wid*16 + (lane >> 2);
    const int r1 = r0 + 8;
    float d0 = 0.f, d1 = 0.f;
    const int dlo = (lane & 3) * 16;
    #pragma unroll
    for (int dd = 0; dd < 16; dd++) {
        int d = dlo + dd;
        float ksv = *(float*)(smem + MP_KS + d*4);
        int b0 = r0*128 + d*2, b1 = r1*128 + d*2;
        int s0 = SWZ(b0), s1 = SWZ(b1);
        float q0v = __bfloat162float(*(__nv_bfloat16*)(smem + MP_QH + s0)) +
                    __bfloat162float(*(__nv_bfloat16*)(smem + MP_QL + s0));
        float q1v = __bfloat162float(*(__nv_bfloat16*)(smem + MP_QH + s1)) +
                    __bfloat162float(*(__nv_bfloat16*)(smem + MP_QL + s1));
        d0 = fmaf(q0v, ksv, d0);
        d1 = fmaf(q1v, ksv, d1);
    }
    #pragma unroll
    for (int off = 1; off <= 2; off <<= 1) {
        rmax0 = fmaxf(rmax0, __shfl_xor_sync(0xffffffffu, rmax0, off));
        rmax1 = fmaxf(rmax1, __shfl_xor_sync(0xffffffffu, rmax1, off));
        d0   += __shfl_xor_sync(0xffffffffu, d0, off);
        d1   += __shfl_xor_sync(0xffffffffu, d1, off);
    }
    if ((lane & 3) == 0) {
        g_M[(size_t)bh*LL + q0 + r0] = (rmax0 - d0*(1.0f/LL)) * 0.125f;
        g_M[(size_t)bh*LL + q0 + r1] = (rmax1 - d1*(1.0f/LL)) * 0.125f;
    }
}

// ================= Kernel 4: top-40 selection (warp-shuffle argmax) =========
__global__ __launch_bounds__(256) void topk_kernel()
{
    const int bh = blockIdx.x, tid = threadIdx.x;
    const int wid = tid >> 5, lid = tid & 31;
    __shared__ float vals[LL];
    __shared__ float rv[8];
    __shared__ int   ri[8];
    for (int i = tid; i < LL; i += 256) vals[i] = g_M[(size_t)bh*LL + i];
    __syncthreads();
    for (int r = 0; r < UU; r++) {
        float bv = -INFINITY; int bi = 0;
        #pragma unroll
        for (int it = 0; it < 8; it++) {
            int i = tid + it*256;
            float v = vals[i];
            if (v > bv || (v == bv && i < bi)) { bv = v; bi = i; }
        }
        #pragma unroll
        for (int off = 16; off > 0; off >>= 1) {
            float ov = __shfl_xor_sync(0xffffffffu, bv, off);
            int   oi = __shfl_xor_sync(0xffffffffu, bi, off);
            if (ov > bv || (ov == bv && oi < bi)) { bv = ov; bi = oi; }
        }
        if (lid == 0) { rv[wid] = bv; ri[wid] = bi; }
        __syncthreads();
        if (tid == 0) {
            float fb = rv[0]; int fi = ri[0];
            #pragma unroll
            for (int w = 1; w < 8; w++)
                if (rv[w] > fb || (rv[w] == fb && ri[w] < fi)) { fb = rv[w]; fi = ri[w]; }
            g_topidx[bh*UU + r] = fi;
            vals[fi] = -INFINITY;
        }
        __syncthreads();
    }
}

// ================= Kernel 5: full attention for active queries =================
__global__ __launch_bounds__(256) void topattn_kernel()
{
    const int bh = blockIdx.y, r = blockIdx.x, tid = threadIdx.x;
    __shared__ float sc[LL];
    __shared__ float qrow[64];
    __shared__ float red[256];
    __shared__ float s_mx, s_sum;

    const int l = g_topidx[bh*UU + r];
    if (tid < 16) {
        float4 qv = *(const float4*)&g_q[((size_t)bh*LL + l)*64 + tid*4];
        *(float4*)&qrow[tid*4] = qv;
    }
    __syncthreads();

    float lmax = -INFINITY;
    #pragma unroll
    for (int it = 0; it < 8; it++) {
        int s = tid + it*256;
        const float4* kp = (const float4*)&g_k[((size_t)bh*LL + s)*64];
        float dot = 0.f;
        #pragma unroll
        for (int c = 0; c < 16; c++) {
            float4 kv = kp[c];
            dot = fmaf(kv.x, qrow[4*c+0], dot);
            dot = fmaf(kv.y, qrow[4*c+1], dot);
            dot = fmaf(kv.z, qrow[4*c+2], dot);
            dot = fmaf(kv.w, qrow[4*c+3], dot);
        }
        dot *= 0.125f;
        sc[s] = dot;
        lmax = fmaxf(lmax, dot);
    }
    red[tid] = lmax; __syncthreads();
    for (int s = 128; s > 0; s >>= 1) {
        if (tid < s) red[tid] = fmaxf(red[tid], red[tid+s]);
        __syncthreads();
    }
    if (tid == 0) s_mx = red[0];
    __syncthreads();

    float lsum = 0.f;
    #pragma unroll
    for (int it = 0; it < 8; it++) {
        int s = tid + it*256;
        float p = expf(sc[s] - s_mx);
        sc[s] = p; lsum += p;
    }
    red[tid] = lsum; __syncthreads();
    for (int s = 128; s > 0; s >>= 1) {
        if (tid < s) red[tid] += red[tid+s];
        __syncthreads();
    }
    if (tid == 0) s_sum = red[0];
    __syncthreads();

    const int d = tid & 63, c = tid >> 6;
    float acc = 0.f;
    for (int s = c*512; s < c*512 + 512; s++)
        acc = fmaf(sc[s], g_v[((size_t)bh*LL + s)*64 + d], acc);
    red[tid] = acc; __syncthreads();
    if (c == 0) {
        float o = (red[d] + red[64+d] + red[128+d] + red[192+d]) / s_sum;
        g_topout[((size_t)bh*UU + r)*64 + d] = o;
    }
}

// ================= Kernel 6: decoder tail (per-batch) =================
__global__ __launch_bounds__(256) void final_kernel(
    const float* __restrict__ Wo, const float* __restrict__ bo,
    const float* __restrict__ W1, const float* __restrict__ b1,
    const float* __restrict__ W2, const float* __restrict__ b2,
    const float* __restrict__ ga1, const float* __restrict__ be1,
    const float* __restrict__ ga2, const float* __restrict__ be2,
    const float* __restrict__ Wout, const float* __restrict__ bout,
    float* __restrict__ d_out)
{
    const int b = blockIdx.x, tid = threadIdx.x;
    __shared__ float ctxm[512], av[512], yv[512], ffv[2048], ov[512], red[256];
    __shared__ float s_m, s_inv;

    #pragma unroll
    for (int k = 0; k < 2; k++) {
        int d = tid + k*256;
        int h = d >> 6, dd = d & 63;
        int bh = b*HH + h;
        float val = g_vmean[bh*64 + dd] * (float)(LL - UU);
        for (int r = 0; r < UU; r++)
            val += g_topout[((size_t)bh*UU + r)*64 + dd];
        ctxm[d] = val * (1.0f/LL);
    }
    __syncthreads();

    #pragma unroll
    for (int k = 0; k < 2; k++) {
        int d = tid + k*256;
        float acc = 0.f;
        for (int e = 0; e < 512; e++)
            acc = fmaf(ctxm[e], Wo[(size_t)e*512 + d], acc);
        av[d] = acc + bo[d];
    }
    __syncthreads();

    red[tid] = 2.f*av[tid] + 2.f*av[tid+256];
    __syncthreads();
    for (int s = 128; s > 0; s >>= 1) { if (tid < s) red[tid] += red[tid+s]; __syncthreads(); }
    if (tid == 0) s_m = red[0] * (1.0f/512.f);
    __syncthreads();
    {
        float t0 = 2.f*av[tid] - s_m, t1 = 2.f*av[tid+256] - s_m;
        red[tid] = t0*t0 + t1*t1;
        __syncthreads();
        for (int s = 128; s > 0; s >>= 1) { if (tid < s) red[tid] += red[tid+s]; __syncthreads(); }
        if (tid == 0) s_inv = 1.0f / sqrtf(red[0]*(1.0f/512.f) + 1e-5f);
        __syncthreads();
        yv[tid]     = t0 * s_inv * ga1[tid]     + be1[tid];
        yv[tid+256] = t1 * s_inv * ga1[tid+256] + be1[tid+256];
    }
    __syncthreads();

    #pragma unroll
    for (int it = 0; it < 8; it++) {
        int f = tid + it*256;
        const float4* wp = (const float4*)&W1[(size_t)f*512];
        float acc = 0.f;
        #pragma unroll 8
        for (int c = 0; c < 128; c++) {
            float4 w = wp[c];
            acc = fmaf(w.x, yv[4*c+0], acc);
            acc = fmaf(w.y, yv[4*c+1], acc);
            acc = fmaf(w.z, yv[4*c+2], acc);
            acc = fmaf(w.w, yv[4*c+3], acc);
        }
        ffv[f] = fmaxf(acc + b1[f], 0.f);
    }
    __syncthreads();

    #pragma unroll
    for (int k = 0; k < 2; k++) {
        int d = tid + k*256;
        const float4* wp = (const float4*)&W2[(size_t)d*2048];
        float acc = 0.f;
        #pragma unroll 8
        for (int c = 0; c < 512; c++) {
            float4 w = wp[c];
            acc = fmaf(w.x, ffv[4*c+0], acc);
            acc = fmaf(w.y, ffv[4*c+1], acc);
            acc = fmaf(w.z, ffv[4*c+2], acc);
            acc = fmaf(w.w, ffv[4*c+3], acc);
        }
        ov[d] = yv[d] + acc + b2[d];
    }
    __syncthreads();

    red[tid] = ov[tid] + ov[tid+256];
    __syncthreads();
    for (int s = 128; s > 0; s >>= 1) { if (tid < s) red[tid] += red[tid+s]; __syncthreads(); }
    if (tid == 0) s_m = red[0] * (1.0f/512.f);
    __syncthreads();
    {
        float t0 = ov[tid] - s_m, t1 = ov[tid+256] - s_m;
        red[tid] = t0*t0 + t1*t1;
        __syncthreads();
        for (int s = 128; s > 0; s >>= 1) { if (tid < s) red[tid] += red[tid+s]; __syncthreads(); }
        if (tid == 0) s_inv = 1.0f / sqrtf(red[0]*(1.0f/512.f) + 1e-5f);
        __syncthreads();
        float o0 = t0 * s_inv * ga2[tid]     + be2[tid];
        float o1 = t1 * s_inv * ga2[tid+256] + be2[tid+256];
        ov[tid] = o0; ov[tid+256] = o1;
        d_out[BB + (size_t)b*512 + tid]       = o0;
        d_out[BB + (size_t)b*512 + tid + 256] = o1;
    }
    __syncthreads();

    red[tid] = ov[tid]*Wout[tid] + ov[tid+256]*Wout[tid+256];
    __syncthreads();
    for (int s = 128; s > 0; s >>= 1) { if (tid < s) red[tid] += red[tid+s]; __syncthreads(); }
    if (tid == 0) d_out[b] = red[0] + bout[0];
}

// ================= host launcher =================
extern "C" void kernel_launch(void* const* d_in, const int* in_sizes, int n_in,
                              void* d_out, int out_size)
{
    const float* x    = (const float*)d_in[0];
    const float* Wq   = (const float*)d_in[1];
    const float* bq   = (const float*)d_in[2];
    const float* Wk   = (const float*)d_in[3];
    const float* bk   = (const float*)d_in[4];
    const float* Wv   = (const float*)d_in[5];
    const float* bv   = (const float*)d_in[6];
    const float* Wo   = (const float*)d_in[7];
    const float* bo   = (const float*)d_in[8];
    const float* W1   = (const float*)d_in[9];
    const float* b1   = (const float*)d_in[10];
    const float* W2   = (const float*)d_in[11];
    const float* b2   = (const float*)d_in[12];
    const float* ga1  = (const float*)d_in[13];
    const float* be1  = (const float*)d_in[14];
    const float* ga2  = (const float*)d_in[15];
    const float* be2  = (const float*)d_in[16];
    const float* Wout = (const float*)d_in[17];
    const float* bout = (const float*)d_in[18];
    float* out = (float*)d_out;

    cudaFuncSetAttribute(maxpass_mma_kernel,
                         cudaFuncAttributeMaxDynamicSharedMemorySize, MP_SMEM);

    dim3 gq(128, 8, 3);
    qkv_kernel<<<gq, 256>>>(x, Wq, bq, Wk, bk, Wv, bv);
    stats_kernel<<<NBH, 256>>>();
    maxpass_mma_kernel<<<dim3(LL/128, NBH), 256, MP_SMEM>>>();
    topk_kernel<<<NBH, 256>>>();
    topattn_kernel<<<dim3(UU, NBH), 256>>>();
    final_kernel<<<BB, 256>>>(Wo, bo, W1, b1, W2, b2,
                              ga1, be1, ga2, be2, Wout, bout, out);
}